// round 6
// baseline (speedup 1.0000x reference)
#include <cuda_runtime.h>
#include <cuda_fp16.h>
#include <cstdint>

// out[b,h] = sum_{d,m} x[b,d,m]*w1[m,h,d]*w2[h,d] + C[h]
//   -> one GEMM: M=256, N=128, K=131072 (k = d*64+m contiguous in x)
//   U[h,k] = w1*w2*256 as single fp16 (err 2^-11); x split exactly fp16 hi+lo
//   out = (xh*U + xl*U)/256 : 2 MMA products.
// mma.sync m16n8k16 f16 (tcgen05 unavailable: harness targets compute_103, no 'a').

static constexpr int Ddim = 2048;
static constexpr int Mhist = 64;
static constexpr int Hdim = 128;
static constexpr int KTOT = Ddim * Mhist;     // 131072
static constexpr int KC = 128;                 // K per chunk (2 sub-tiles of 64)
static constexpr int NCHUNK = KTOT / KC;       // 1024
static constexpr int KSPLIT = 74;              // grid.x ; grid.y = 2 -> 148 CTAs
static constexpr float USCALE = 256.0f;
static constexpr float UINV = 1.0f / 256.0f;

__device__ __half g_U[(size_t)Hdim * KTOT];    // 32 MB
__device__ float g_C[Hdim];

__device__ __forceinline__ uint32_t smem_u32(const void* p) {
    uint32_t a;
    asm("{ .reg .u64 t; cvta.to.shared.u64 t, %1; cvt.u32.u64 %0, t; }" : "=r"(a) : "l"(p));
    return a;
}
__device__ __forceinline__ uint32_t sw128(uint32_t off) { return off ^ ((off >> 3) & 0x70); }
__device__ __forceinline__ uint32_t h2_bits(__half2 v) {
    return reinterpret_cast<uint32_t&>(v);
}
__device__ __forceinline__ void ldsm_x4(uint32_t& r0, uint32_t& r1, uint32_t& r2, uint32_t& r3,
                                        uint32_t addr) {
    asm volatile("ldmatrix.sync.aligned.m8n8.x4.shared.b16 {%0,%1,%2,%3}, [%4];"
                 : "=r"(r0), "=r"(r1), "=r"(r2), "=r"(r3) : "r"(addr));
}
__device__ __forceinline__ void mma16816(float* c, const uint32_t* a, const uint32_t* b) {
    asm volatile(
        "mma.sync.aligned.m16n8k16.row.col.f32.f16.f16.f32 "
        "{%0,%1,%2,%3}, {%4,%5,%6,%7}, {%8,%9}, {%0,%1,%2,%3};"
        : "+f"(c[0]), "+f"(c[1]), "+f"(c[2]), "+f"(c[3])
        : "r"(a[0]), "r"(a[1]), "r"(a[2]), "r"(a[3]), "r"(b[0]), "r"(b[1]));
}
__device__ __forceinline__ void cp_async16(uint32_t dst, const void* src) {
    asm volatile("cp.async.cg.shared.global [%0], [%1], 16;" :: "r"(dst), "l"(src));
}
#define CP_COMMIT() asm volatile("cp.async.commit_group;" ::: "memory")
#define CP_WAIT_ALL() asm volatile("cp.async.wait_group 0;" ::: "memory")

// ---------------- precompute ----------------
__global__ void build_u_kernel(const float* __restrict__ w1, const float* __restrict__ w2) {
    __shared__ uint32_t st[8][33 * 32];
    int g = blockIdx.x * blockDim.x + threadIdx.x;  // 0 .. 128*2048-1
    int w = threadIdx.x >> 5;
    int lane = threadIdx.x & 31;
    int h = g >> 11;
    int d = g & 2047;
    float s = w2[h * Ddim + d] * USCALE;
    uint32_t uu[32];
#pragma unroll 16
    for (int m = 0; m < Mhist; m += 2) {
        float a = w1[((size_t)m * Hdim + h) * Ddim + d] * s;
        float b = w1[((size_t)(m + 1) * Hdim + h) * Ddim + d] * s;
        uu[m >> 1] = h2_bits(__floats2half2_rn(a, b));
    }
    int d0 = d & ~31;
    uint32_t* ou = reinterpret_cast<uint32_t*>(g_U) + (size_t)h * (KTOT / 2) + (size_t)d0 * 32;
#pragma unroll
    for (int j = 0; j < 32; j++) st[w][lane * 33 + j] = uu[j];
    __syncwarp();
#pragma unroll
    for (int i = 0; i < 32; i++) ou[i * 32 + lane] = st[w][i * 33 + lane];
}

__global__ void bias_kernel(const float* __restrict__ b1, const float* __restrict__ w2,
                            const float* __restrict__ b2, float* __restrict__ out) {
    __shared__ float red[256];
    int h = blockIdx.x;
    float s = 0.0f;
    for (int d = threadIdx.x; d < Ddim; d += 256)
        s += b1[h * Ddim + d] * w2[h * Ddim + d];
    red[threadIdx.x] = s;
    __syncthreads();
    for (int st = 128; st > 0; st >>= 1) {
        if (threadIdx.x < st) red[threadIdx.x] += red[threadIdx.x + st];
        __syncthreads();
    }
    __syncthreads();
    float C = red[0] + b2[h];
    out[(size_t)threadIdx.x * Hdim + h] = C;
    if (threadIdx.x == 0) g_C[h] = C;
}

// ---------------- GEMM ----------------
// 512 threads = 16 warps (4x4), CTA tile 128x128, warp tile 32x32, KC=128.
// stage = {A_hi 32K (2 sub-tiles), A_lo 32K, B 32K} = 96KB; 2 stages = 192KB.
static constexpr int SUBT = 16384;             // 64-col sub-tile size
static constexpr int S_AHI = 0;
static constexpr int S_ALO = 32768;
static constexpr int S_B = 65536;
static constexpr int STAGE = 98304;
static constexpr int SMEM_TOTAL = 2 * STAGE;   // 196608

// convert 32 fp32 -> 32 fp16 hi + lo; 4x16B stores each into one sub-tile slot
__device__ __forceinline__ void sts_A(char* smem, uint32_t stg, uint32_t subt_off,
                                      const float4* v, const uint32_t* oA) {
    uint32_t h[16], l[16];
#pragma unroll
    for (int j = 0; j < 8; j++) {
        float4 t = v[j];
        __half2 H01 = __floats2half2_rn(t.x, t.y);
        float2 b01 = __half22float2(H01);
        __half2 L01 = __floats2half2_rn(t.x - b01.x, t.y - b01.y);
        __half2 H23 = __floats2half2_rn(t.z, t.w);
        float2 b23 = __half22float2(H23);
        __half2 L23 = __floats2half2_rn(t.z - b23.x, t.w - b23.y);
        h[2 * j] = h2_bits(H01); h[2 * j + 1] = h2_bits(H23);
        l[2 * j] = h2_bits(L01); l[2 * j + 1] = h2_bits(L23);
    }
#pragma unroll
    for (int i = 0; i < 4; i++) {
        uint4 vh; vh.x = h[4 * i]; vh.y = h[4 * i + 1]; vh.z = h[4 * i + 2]; vh.w = h[4 * i + 3];
        uint4 vl; vl.x = l[4 * i]; vl.y = l[4 * i + 1]; vl.z = l[4 * i + 2]; vl.w = l[4 * i + 3];
        *reinterpret_cast<uint4*>(smem + stg + S_AHI + subt_off + oA[i]) = vh;
        *reinterpret_cast<uint4*>(smem + stg + S_ALO + subt_off + oA[i]) = vl;
    }
}

__global__ void __launch_bounds__(512, 1)
gemm_kernel(const float* __restrict__ x, float* __restrict__ out) {
    extern __shared__ char smem[];
    uint32_t sb = smem_u32(smem);
    int tid = threadIdx.x;
    int wid = tid >> 5;
    int lane = tid & 31;
    int warp_m = wid >> 2;
    int warp_n = wid & 3;
    int ksp = blockIdx.x;
    int mtile = blockIdx.y;

    int c0 = (ksp * NCHUNK) / KSPLIT;
    int c1 = ((ksp + 1) * NCHUNK) / KSPLIT;

    // loader: row = tid>>2 (0..127), seg = tid&3 -> 32 cols each
    int arow = tid >> 2;
    int seg = tid & 3;
    uint32_t subt_off = (uint32_t)(seg >> 1) * SUBT;   // which 64-col sub-tile
    int sc = seg & 1;                                   // 32-col half within sub-tile
    const float* xr = x + ((size_t)(mtile * 128 + arow)) * KTOT + seg * 32;
    const __half* ub = g_U + (size_t)arow * KTOT + seg * 32;

    uint32_t oA[4];
#pragma unroll
    for (int i = 0; i < 4; i++)
        oA[i] = sw128((uint32_t)(arow * 128 + sc * 64 + i * 16));

    uint32_t a_row_l = (uint32_t)(warp_m * 32 + (lane & 15));
    uint32_t a_kb_l = (uint32_t)((lane >> 4) * 16);
    uint32_t b_row_l = (uint32_t)(warp_n * 32 + ((lane >> 4) << 3) + (lane & 7));
    uint32_t b_kb_l = (uint32_t)(((lane >> 3) & 1) * 16);

    float acc[2][4][4];
#pragma unroll
    for (int i = 0; i < 2; i++)
#pragma unroll
        for (int j = 0; j < 4; j++)
#pragma unroll
            for (int r = 0; r < 4; r++) acc[i][j][r] = 0.0f;

    float4 xa[8];

    // ---- prologue: chunk c0 -> stage0 ----
    {
        const float4* xp = reinterpret_cast<const float4*>(xr + (size_t)c0 * KC);
#pragma unroll
        for (int j = 0; j < 8; j++) xa[j] = xp[j];
        const __half* up = ub + (size_t)c0 * KC;
#pragma unroll
        for (int i = 0; i < 4; i++)
            cp_async16(sb + S_B + subt_off + oA[i], up + 8 * i);
        CP_COMMIT();
        sts_A(smem, 0, subt_off, xa, oA);
    }

    for (int c = c0; c < c1; c++) {
        uint32_t stg = (uint32_t)((c - c0) & 1) * STAGE;
        uint32_t nstg = stg ^ STAGE;

        CP_WAIT_ALL();           // B(c) landed
        __syncthreads();         // stage(c) ready; other stage's readers done

        bool more = (c + 1 < c1);
        if (more) {
            // issue x(c+1) LDG now; consumed by sts_A after the MMA block
            const float4* xp = reinterpret_cast<const float4*>(xr + (size_t)(c + 1) * KC);
#pragma unroll
            for (int j = 0; j < 8; j++) xa[j] = xp[j];
            const __half* up = ub + (size_t)(c + 1) * KC;
#pragma unroll
            for (int i = 0; i < 4; i++)
                cp_async16(sb + nstg + S_B + subt_off + oA[i], up + 8 * i);
            CP_COMMIT();
        }

        // ---- MMA on stage(c): 2 sub-tiles x 4 k-steps x 2 products ----
        uint32_t Ahi = sb + stg + S_AHI, Alo = sb + stg + S_ALO, Bb = sb + stg + S_B;
#pragma unroll
        for (int kk = 0; kk < 2; kk++) {
            uint32_t kb = (uint32_t)kk * SUBT;
#pragma unroll
            for (int ks = 0; ks < 4; ks++) {
                uint32_t boff0 = kb + sw128(b_row_l * 128 + ks * 32 + b_kb_l);
                uint32_t boff1 = kb + sw128((b_row_l + 16) * 128 + ks * 32 + b_kb_l);
                uint32_t aoff0 = kb + sw128(a_row_l * 128 + ks * 32 + a_kb_l);
                uint32_t aoff1 = kb + sw128((a_row_l + 16) * 128 + ks * 32 + a_kb_l);
                uint32_t bh[4][2], ah[2][4], al[2][4];
                ldsm_x4(bh[0][0], bh[0][1], bh[1][0], bh[1][1], Bb + boff0);
                ldsm_x4(bh[2][0], bh[2][1], bh[3][0], bh[3][1], Bb + boff1);
                ldsm_x4(ah[0][0], ah[0][1], ah[0][2], ah[0][3], Ahi + aoff0);
                ldsm_x4(ah[1][0], ah[1][1], ah[1][2], ah[1][3], Ahi + aoff1);
#pragma unroll
                for (int mf = 0; mf < 2; mf++)
#pragma unroll
                    for (int nf = 0; nf < 4; nf++)
                        mma16816(acc[mf][nf], ah[mf], bh[nf]);      // xh * U
                ldsm_x4(al[0][0], al[0][1], al[0][2], al[0][3], Alo + aoff0);
                ldsm_x4(al[1][0], al[1][1], al[1][2], al[1][3], Alo + aoff1);
#pragma unroll
                for (int mf = 0; mf < 2; mf++)
#pragma unroll
                    for (int nf = 0; nf < 4; nf++)
                        mma16816(acc[mf][nf], al[mf], bh[nf]);      // xl * U
            }
        }

        if (more)
            sts_A(smem, nstg, subt_off, xa, oA);   // x(c+1) LDG completed under MMA
    }

    // ---- epilogue: unscale + split-K atomic reduce (out pre-filled with bias) ----
    int r0 = mtile * 128 + warp_m * 32 + (lane >> 2);
    int cc0 = warp_n * 32 + (lane & 3) * 2;
#pragma unroll
    for (int mf = 0; mf < 2; mf++) {
#pragma unroll
        for (int nf = 0; nf < 4; nf++) {
            int row = r0 + mf * 16;
            int col = cc0 + nf * 8;
            atomicAdd(out + (size_t)row * Hdim + col,           acc[mf][nf][0] * UINV);
            atomicAdd(out + (size_t)row * Hdim + col + 1,       acc[mf][nf][1] * UINV);
            atomicAdd(out + (size_t)(row + 8) * Hdim + col,     acc[mf][nf][2] * UINV);
            atomicAdd(out + (size_t)(row + 8) * Hdim + col + 1, acc[mf][nf][3] * UINV);
        }
    }
}

// ---------------- launch ----------------
extern "C" void kernel_launch(void* const* d_in, const int* in_sizes, int n_in,
                              void* d_out, int out_size) {
    const float* x  = (const float*)d_in[0];
    const float* w1 = (const float*)d_in[1];
    const float* b1 = (const float*)d_in[2];
    const float* w2 = (const float*)d_in[3];
    const float* b2 = (const float*)d_in[4];
    float* out = (float*)d_out;

    cudaFuncSetAttribute(gemm_kernel, cudaFuncAttributeMaxDynamicSharedMemorySize, SMEM_TOTAL);

    build_u_kernel<<<(Hdim * Ddim) / 256, 256>>>(w1, w2);
    bias_kernel<<<Hdim, 256>>>(b1, w2, b2, out);
    dim3 grid(KSPLIT, 2);
    gemm_kernel<<<grid, 512, SMEM_TOTAL>>>(x, out);
}

// round 8
// speedup vs baseline: 1.2216x; 1.2216x over previous
#include <cuda_runtime.h>
#include <cuda_fp16.h>
#include <cstdint>

// out[b,h] = sum_{d,m} x[b,d,m]*w1[m,h,d]*w2[h,d] + C[h]
//   -> one GEMM: M=256, N=128, K=131072 (k = d*64+m contiguous in x)
//   U[h,k] = w1*w2*256 as single fp16 (err 2^-11); x split exactly fp16 hi+lo
//   out = (xh*U + xl*U)/256 : 2 MMA products.
// A kept fp32 in smem (cp.async), converted to hi/lo in regs inside MMA loop.
// mma.sync m16n8k16 f16 (tcgen05 unavailable: harness targets compute_103, no 'a').

static constexpr int Ddim = 2048;
static constexpr int Mhist = 64;
static constexpr int Hdim = 128;
static constexpr int KTOT = Ddim * Mhist;     // 131072
static constexpr int KC = 64;                  // K per chunk
static constexpr int NCHUNK = KTOT / KC;       // 2048
static constexpr int KSPLIT = 74;              // grid.x ; grid.y = 2 -> 148 CTAs
static constexpr float USCALE = 256.0f;
static constexpr float UINV = 1.0f / 256.0f;

__device__ __half g_U[(size_t)Hdim * KTOT];    // 32 MB
__device__ float g_C[Hdim];

__device__ __forceinline__ uint32_t smem_u32(const void* p) {
    uint32_t a;
    asm("{ .reg .u64 t; cvta.to.shared.u64 t, %1; cvt.u32.u64 %0, t; }" : "=r"(a) : "l"(p));
    return a;
}
__device__ __forceinline__ uint32_t sw128(uint32_t off) { return off ^ ((off >> 3) & 0x70); }
// fp32 A tile: 256B rows, XOR-swizzle 32B granules by row%8 (conflict-free LDS.64)
__device__ __forceinline__ uint32_t aswz(uint32_t row, uint32_t byte) {
    return row * 256 + (byte ^ ((row & 7) << 5));
}
__device__ __forceinline__ uint32_t h2_bits(__half2 v) {
    return reinterpret_cast<uint32_t&>(v);
}
__device__ __forceinline__ void ldsm_x4(uint32_t& r0, uint32_t& r1, uint32_t& r2, uint32_t& r3,
                                        uint32_t addr) {
    asm volatile("ldmatrix.sync.aligned.m8n8.x4.shared.b16 {%0,%1,%2,%3}, [%4];"
                 : "=r"(r0), "=r"(r1), "=r"(r2), "=r"(r3) : "r"(addr));
}
__device__ __forceinline__ float2 lds64(uint32_t addr) {
    float2 v;
    asm volatile("ld.shared.v2.f32 {%0,%1}, [%2];" : "=f"(v.x), "=f"(v.y) : "r"(addr));
    return v;
}
__device__ __forceinline__ void mma16816(float* c, const uint32_t* a, const uint32_t* b) {
    asm volatile(
        "mma.sync.aligned.m16n8k16.row.col.f32.f16.f16.f32 "
        "{%0,%1,%2,%3}, {%4,%5,%6,%7}, {%8,%9}, {%0,%1,%2,%3};"
        : "+f"(c[0]), "+f"(c[1]), "+f"(c[2]), "+f"(c[3])
        : "r"(a[0]), "r"(a[1]), "r"(a[2]), "r"(a[3]), "r"(b[0]), "r"(b[1]));
}
__device__ __forceinline__ void cp_async16(uint32_t dst, const void* src) {
    asm volatile("cp.async.cg.shared.global [%0], [%1], 16;" :: "r"(dst), "l"(src));
}
#define CP_COMMIT() asm volatile("cp.async.commit_group;" ::: "memory")
#define CP_WAIT_2() asm volatile("cp.async.wait_group 2;" ::: "memory")

// ---------------- precompute ----------------
__global__ void build_u_kernel(const float* __restrict__ w1, const float* __restrict__ w2) {
    __shared__ uint32_t st[8][33 * 32];
    int g = blockIdx.x * blockDim.x + threadIdx.x;  // 0 .. 128*2048-1
    int w = threadIdx.x >> 5;
    int lane = threadIdx.x & 31;
    int h = g >> 11;
    int d = g & 2047;
    float s = w2[h * Ddim + d] * USCALE;
    uint32_t uu[32];
#pragma unroll 16
    for (int m = 0; m < Mhist; m += 2) {
        float a = w1[((size_t)m * Hdim + h) * Ddim + d] * s;
        float b = w1[((size_t)(m + 1) * Hdim + h) * Ddim + d] * s;
        uu[m >> 1] = h2_bits(__floats2half2_rn(a, b));
    }
    int d0 = d & ~31;
    uint32_t* ou = reinterpret_cast<uint32_t*>(g_U) + (size_t)h * (KTOT / 2) + (size_t)d0 * 32;
#pragma unroll
    for (int j = 0; j < 32; j++) st[w][lane * 33 + j] = uu[j];
    __syncwarp();
#pragma unroll
    for (int i = 0; i < 32; i++) ou[i * 32 + lane] = st[w][i * 33 + lane];
}

__global__ void bias_kernel(const float* __restrict__ b1, const float* __restrict__ w2,
                            const float* __restrict__ b2, float* __restrict__ out) {
    __shared__ float red[256];
    int h = blockIdx.x;
    float s = 0.0f;
    for (int d = threadIdx.x; d < Ddim; d += 256)
        s += b1[h * Ddim + d] * w2[h * Ddim + d];
    red[threadIdx.x] = s;
    __syncthreads();
    for (int st = 128; st > 0; st >>= 1) {
        if (threadIdx.x < st) red[threadIdx.x] += red[threadIdx.x + st];
        __syncthreads();
    }
    __syncthreads();
    float C = red[0] + b2[h];
    out[(size_t)threadIdx.x * Hdim + h] = C;
    if (threadIdx.x == 0) g_C[h] = C;
}

// ---------------- GEMM ----------------
// 512 threads = 16 warps (4x4), CTA tile 128x128, warp tile 32x32.
// stage = {A fp32 32K, B fp16 16K} = 48KB; 4 stages = 192KB. 3 chunks in flight.
static constexpr int S_B = 32768;              // B offset within stage
static constexpr int STAGE = 49152;
static constexpr int NSTAGE = 4;
static constexpr int SMEM_TOTAL = NSTAGE * STAGE;  // 196608

__global__ void __launch_bounds__(512, 1)
gemm_kernel(const float* __restrict__ x, float* __restrict__ out) {
    extern __shared__ char smem[];
    uint32_t sb = smem_u32(smem);
    int tid = threadIdx.x;
    int wid = tid >> 5;
    int lane = tid & 31;
    int warp_m = wid >> 2;
    int warp_n = wid & 3;
    int ksp = blockIdx.x;
    int mtile = blockIdx.y;

    int c0 = (ksp * NCHUNK) / KSPLIT;
    int c1 = ((ksp + 1) * NCHUNK) / KSPLIT;

    // loader: row = tid>>2 (0..127), q = tid&3 (16-col quarter)
    int arow = tid >> 2;
    int q = tid & 3;
    const float* xr = x + ((size_t)(mtile * 128 + arow)) * KTOT + q * 16;
    const __half* ub = g_U + (size_t)arow * KTOT + q * 16;

    // cp.async dst offsets (within stage)
    uint32_t aoA[4];
#pragma unroll
    for (int i = 0; i < 4; i++)
        aoA[i] = aswz((uint32_t)arow, (uint32_t)(q * 64 + i * 16));
    uint32_t boA[2];
    boA[0] = sw128((uint32_t)(arow * 128 + q * 32));
    boA[1] = sw128((uint32_t)(arow * 128 + q * 32 + 16));

    // fragment address components
    int rl = lane >> 2;                         // 0..7
    uint32_t cxor = (uint32_t)(rl << 5);
    uint32_t cb = (uint32_t)((lane & 3) * 8);   // byte offset of fp32 pair
    // A fp32 row-base (per mf), without stage
    uint32_t arow0 = (uint32_t)((warp_m * 32 + rl) * 256);
    uint32_t b_row_l = (uint32_t)(warp_n * 32 + ((lane >> 4) << 3) + (lane & 7));
    uint32_t b_kb_l = (uint32_t)(((lane >> 3) & 1) * 16);

    float acc[2][4][4];
#pragma unroll
    for (int i = 0; i < 2; i++)
#pragma unroll
        for (int j = 0; j < 4; j++)
#pragma unroll
            for (int r = 0; r < 4; r++) acc[i][j][r] = 0.0f;

    // ---- prologue: issue 3 stages ----
#pragma unroll
    for (int pi = 0; pi < 3; pi++) {
        int c = c0 + pi;                        // c1-c0 >= 27, always valid
        uint32_t st = (uint32_t)pi * STAGE;
        const float* xp = xr + (size_t)c * KC;
        const __half* up = ub + (size_t)c * KC;
#pragma unroll
        for (int i = 0; i < 4; i++) cp_async16(sb + st + aoA[i], xp + i * 4);
        cp_async16(sb + st + S_B + boA[0], up);
        cp_async16(sb + st + S_B + boA[1], up + 8);
        CP_COMMIT();
    }

    for (int c = c0; c < c1; c++) {
        uint32_t stg = (uint32_t)((c - c0) & 3) * STAGE;

        CP_WAIT_2();             // stage(c) landed (2 newer groups may be in flight)
        __syncthreads();         // all threads see stage(c); MMA(c-1) readers done

        int cn = c + 3;
        if (cn < c1) {
            uint32_t nst = (uint32_t)((cn - c0) & 3) * STAGE;
            const float* xp = xr + (size_t)cn * KC;
            const __half* up = ub + (size_t)cn * KC;
#pragma unroll
            for (int i = 0; i < 4; i++) cp_async16(sb + nst + aoA[i], xp + i * 4);
            cp_async16(sb + nst + S_B + boA[0], up);
            cp_async16(sb + nst + S_B + boA[1], up + 8);
        }
        CP_COMMIT();             // keep group counting uniform

        // ---- MMA on stage(c) ----
        uint32_t Ab = sb + stg;
        uint32_t Bb = sb + stg + S_B;
#pragma unroll
        for (int ks = 0; ks < 4; ks++) {
            // B fragments (fp16, ldmatrix)
            uint32_t bh[4][2];
            ldsm_x4(bh[0][0], bh[0][1], bh[1][0], bh[1][1],
                    Bb + sw128(b_row_l * 128 + ks * 32 + b_kb_l));
            ldsm_x4(bh[2][0], bh[2][1], bh[3][0], bh[3][1],
                    Bb + sw128((b_row_l + 16) * 128 + ks * 32 + b_kb_l));
            // A fragments: LDS.64 fp32, convert to hi/lo half2 in regs
            uint32_t ah[2][4], al[2][4];
#pragma unroll
            for (int mf = 0; mf < 2; mf++) {
                uint32_t base = Ab + arow0 + (uint32_t)(mf * 16 * 256);
                uint32_t c00 = (uint32_t)(ks * 64) + cb;
#pragma unroll
                for (int fi = 0; fi < 4; fi++) {
                    // fi: 0=(r,c) 1=(r+8,c) 2=(r,c+8) 3=(r+8,c+8)
                    uint32_t addr = base + ((fi & 1) ? 2048u : 0u)
                                  + ((c00 + ((fi >> 1) ? 32u : 0u)) ^ cxor);
                    float2 v = lds64(addr);
                    __half2 H = __floats2half2_rn(v.x, v.y);
                    float2 hf = __half22float2(H);
                    __half2 L = __floats2half2_rn(v.x - hf.x, v.y - hf.y);
                    ah[mf][fi] = h2_bits(H);
                    al[mf][fi] = h2_bits(L);
                }
            }
#pragma unroll
            for (int mf = 0; mf < 2; mf++)
#pragma unroll
                for (int nf = 0; nf < 4; nf++)
                    mma16816(acc[mf][nf], ah[mf], bh[nf]);      // xh * U
#pragma unroll
            for (int mf = 0; mf < 2; mf++)
#pragma unroll
                for (int nf = 0; nf < 4; nf++)
                    mma16816(acc[mf][nf], al[mf], bh[nf]);      // xl * U
        }
    }

    // ---- epilogue: unscale + split-K atomic reduce (out pre-filled with bias) ----
    int r0 = mtile * 128 + warp_m * 32 + (lane >> 2);
    int cc0 = warp_n * 32 + (lane & 3) * 2;
#pragma unroll
    for (int mf = 0; mf < 2; mf++) {
#pragma unroll
        for (int nf = 0; nf < 4; nf++) {
            int row = r0 + mf * 16;
            int col = cc0 + nf * 8;
            atomicAdd(out + (size_t)row * Hdim + col,           acc[mf][nf][0] * UINV);
            atomicAdd(out + (size_t)row * Hdim + col + 1,       acc[mf][nf][1] * UINV);
            atomicAdd(out + (size_t)(row + 8) * Hdim + col,     acc[mf][nf][2] * UINV);
            atomicAdd(out + (size_t)(row + 8) * Hdim + col + 1, acc[mf][nf][3] * UINV);
        }
    }
}

// ---------------- launch ----------------
extern "C" void kernel_launch(void* const* d_in, const int* in_sizes, int n_in,
                              void* d_out, int out_size) {
    const float* x  = (const float*)d_in[0];
    const float* w1 = (const float*)d_in[1];
    const float* b1 = (const float*)d_in[2];
    const float* w2 = (const float*)d_in[3];
    const float* b2 = (const float*)d_in[4];
    float* out = (float*)d_out;

    cudaFuncSetAttribute(gemm_kernel, cudaFuncAttributeMaxDynamicSharedMemorySize, SMEM_TOTAL);

    build_u_kernel<<<(Hdim * Ddim) / 256, 256>>>(w1, w2);
    bias_kernel<<<Hdim, 256>>>(b1, w2, b2, out);
    dim3 grid(KSPLIT, 2);
    gemm_kernel<<<grid, 512, SMEM_TOTAL>>>(x, out);
}